// round 11
// baseline (speedup 1.0000x reference)
#include <cuda_runtime.h>
#include <math.h>
#include <stdint.h>

#define Bz 8
#define Nn 4096
#define Mm 2048
#define H2 128
#define KN 32
#define CAP 512
#define NC 4096   // 16^3 morton cells

__device__ float g_A[Bz * Nn * 64];     // x @ W1[:64] + b1
__device__ int   g_idx[Bz * Mm];        // FPS indices
__device__ int   g_nbr[Bz * Mm * KN];   // in-radius neighbors, front-packed, -1 pad
// morton-sorted point data exported by k1 for k2's grid search
__device__ float g_sx[Bz * Nn];
__device__ float g_sy[Bz * Nn];
__device__ float g_sz[Bz * Nn];
__device__ int   g_sor[Bz * Nn];
__device__ int   g_cst[Bz * (NC + 1)];

__device__ __forceinline__ unsigned long long umax64(unsigned long long a, unsigned long long b){return a>b?a:b;}
__device__ __forceinline__ unsigned long long umin64(unsigned long long a, unsigned long long b){return a<b?a:b;}

// packed f32x2 helpers (rn rounding identical to scalar)
__device__ __forceinline__ unsigned long long pk2(float lo, float hi){
    unsigned long long r; asm("mov.b64 %0, {%1, %2};" : "=l"(r) : "f"(lo), "f"(hi)); return r;
}
__device__ __forceinline__ void upk2(unsigned long long v, float& lo, float& hi){
    asm("mov.b64 {%0, %1}, %2;" : "=f"(lo), "=f"(hi) : "l"(v));
}
__device__ __forceinline__ unsigned long long addx2(unsigned long long a, unsigned long long b){
    unsigned long long r; asm("add.rn.f32x2 %0, %1, %2;" : "=l"(r) : "l"(a), "l"(b)); return r;
}
__device__ __forceinline__ unsigned long long mulx2(unsigned long long a, unsigned long long b){
    unsigned long long r; asm("mul.rn.f32x2 %0, %1, %2;" : "=l"(r) : "l"(a), "l"(b)); return r;
}
__device__ __forceinline__ unsigned long long fmax2(unsigned long long a, unsigned long long b, unsigned long long c){
    unsigned long long r; asm("fma.rn.f32x2 %0, %1, %2, %3;" : "=l"(r) : "l"(a), "l"(b), "l"(c)); return r;
}

__device__ __forceinline__ int mspread4(int v){  // 4-bit spread for 16^3 morton
    return (v & 1) | ((v & 2) << 2) | ((v & 4) << 4) | ((v & 8) << 6);
}

// ---------------- K0: A = x @ W1[0:64,:] + b1 ----------------
__global__ void __launch_bounds__(256) k0_feat(const float* __restrict__ x,
                                               const float* __restrict__ W1,
                                               const float* __restrict__ b1) {
    __shared__ float xs[4 * 64];
    int t = threadIdx.x;
    int c = t & 63, rs = t >> 6;
    float w[64];
#pragma unroll
    for (int f = 0; f < 64; f++) w[f] = W1[f * 64 + c];
    float bb = b1[c];
    int base = blockIdx.x * 128;
    const float4* xs4 = (const float4*)xs;
    for (int r0 = 0; r0 < 128; r0 += 4) {
        int row = base + r0 + rs;
        __syncthreads();
        xs[rs * 64 + c] = x[(size_t)row * 64 + c];
        __syncthreads();
        float a0 = bb, a1 = 0.f, a2 = 0.f, a3 = 0.f;
#pragma unroll
        for (int q = 0; q < 16; q++) {
            float4 xv = xs4[rs * 16 + q];
            a0 = fmaf(xv.x, w[4*q+0], a0);
            a1 = fmaf(xv.y, w[4*q+1], a1);
            a2 = fmaf(xv.z, w[4*q+2], a2);
            a3 = fmaf(xv.w, w[4*q+3], a3);
        }
        g_A[(size_t)row * 64 + c] = (a0 + a1) + (a2 + a3);
    }
}

// ---------------- K1: FPS (R8 engine) + export sorted grid for k2 ----------------
// md update arithmetic bit-identical to the passing brute-force version.
__global__ void __launch_bounds__(256) k1_fps(const float* __restrict__ pos) {
    extern __shared__ char sm1c[];
    unsigned long long* swk = (unsigned long long*)sm1c;       // [2][8]
    float4* op4 = (float4*)(sm1c + 128);                       // [Nn] original order
    float* sx = (float*)(sm1c + 128 + Nn * 16);                // morton-sorted
    float* sy = sx + Nn;
    float* sz = sy + Nn;
    int* sorig  = (int*)(sz + Nn);
    int* cstart = sorig + Nn;      // NC+1
    int* ccnt   = cstart + NC + 1; // NC
    int* stmp   = ccnt + NC;       // 256

    int b = blockIdx.x, t = threadIdx.x;
    int w = t >> 5, lane = t & 31;
    const float* p = pos + (size_t)b * Nn * 3;

    for (int i = t; i < Nn; i += 256)
        op4[i] = make_float4(p[i*3], p[i*3+1], p[i*3+2], 0.f);
    for (int i = t; i < NC; i += 256) ccnt[i] = 0;
    __syncthreads();
    for (int i = t; i < Nn; i += 256) {
        float4 q = op4[i];
        int ix = min(15, max(0, (int)(q.x * 16.0f)));
        int iy = min(15, max(0, (int)(q.y * 16.0f)));
        int iz = min(15, max(0, (int)(q.z * 16.0f)));
        atomicAdd(&ccnt[mspread4(ix) | (mspread4(iy) << 1) | (mspread4(iz) << 2)], 1);
    }
    __syncthreads();
    int psum = 0;
#pragma unroll
    for (int k = 0; k < 16; k++) psum += ccnt[t * 16 + k];
    stmp[t] = psum;
    __syncthreads();
    for (int off = 1; off < 256; off <<= 1) {
        int v = stmp[t];
        if (t >= off) v += stmp[t - off];
        __syncthreads();
        stmp[t] = v;
        __syncthreads();
    }
    int run = stmp[t] - psum;
#pragma unroll
    for (int k = 0; k < 16; k++) {
        int c = ccnt[t * 16 + k];
        cstart[t * 16 + k] = run;
        g_cst[b * (NC + 1) + t * 16 + k] = run;
        run += c;
    }
    if (t == 255) { cstart[NC] = Nn; g_cst[b * (NC + 1) + NC] = Nn; }
    __syncthreads();
    for (int i = t; i < NC; i += 256) ccnt[i] = 0;
    __syncthreads();
    for (int i = t; i < Nn; i += 256) {
        float4 q = op4[i];
        int ix = min(15, max(0, (int)(q.x * 16.0f)));
        int iy = min(15, max(0, (int)(q.y * 16.0f)));
        int iz = min(15, max(0, (int)(q.z * 16.0f)));
        int c = mspread4(ix) | (mspread4(iy) << 1) | (mspread4(iz) << 2);
        int dst = cstart[c] + atomicAdd(&ccnt[c], 1);
        sx[dst] = q.x; sy[dst] = q.y; sz[dst] = q.z;
        sorig[dst] = i;
        g_sx[b * Nn + dst] = q.x; g_sy[b * Nn + dst] = q.y; g_sz[b * Nn + dst] = q.z;
        g_sor[b * Nn + dst] = i;
    }
    if (t == 0) g_idx[b * Mm] = 0;
    __syncthreads();

    // pack 16 sorted points per thread as 8 f32x2 pairs; tight bbox in regs
    unsigned long long PX[8], PY[8], PZ[8];
    float md[16];
    unsigned NO[16];
    int base = t * 16;
    float bx0 = 1e30f, bx1 = -1e30f, by0 = 1e30f, by1 = -1e30f, bz0 = 1e30f, bz1 = -1e30f;
#pragma unroll
    for (int q = 0; q < 8; q++) {
        float a0 = sx[base + 2*q], a1 = sx[base + 2*q + 1];
        float c0 = sy[base + 2*q], c1 = sy[base + 2*q + 1];
        float d0 = sz[base + 2*q], d1 = sz[base + 2*q + 1];
        PX[q] = pk2(a0, a1); PY[q] = pk2(c0, c1); PZ[q] = pk2(d0, d1);
        bx0 = fminf(bx0, fminf(a0, a1)); bx1 = fmaxf(bx1, fmaxf(a0, a1));
        by0 = fminf(by0, fminf(c0, c1)); by1 = fmaxf(by1, fmaxf(c0, c1));
        bz0 = fminf(bz0, fminf(d0, d1)); bz1 = fmaxf(bz1, fmaxf(d0, d1));
        NO[2*q]   = ~(unsigned)sorig[base + 2*q];
        NO[2*q+1] = ~(unsigned)sorig[base + 2*q + 1];
        md[2*q] = __int_as_float(0x7f800000);
        md[2*q+1] = __int_as_float(0x7f800000);
    }
    unsigned long long key = 0;
#pragma unroll
    for (int i = 0; i < 16; i++)
        key = umax64(key, (0x7f800000ULL << 32) | NO[i]);

    float4 ctr = op4[0];
    float lx = ctr.x, ly = ctr.y, lz = ctr.z;
    unsigned par = 0;

    for (int m = 1; m < Mm; m++) {
        float vmax = __uint_as_float((unsigned)(key >> 32));
        float lbx = fmaxf(fmaxf(bx0 - lx, lx - bx1), 0.f);
        float lby = fmaxf(fmaxf(by0 - ly, ly - by1), 0.f);
        float lbz = fmaxf(fmaxf(bz0 - lz, lz - bz1), 0.f);
        float lb2 = (lbx*lbx + lby*lby + lbz*lbz) * 0.999f;
        if (lb2 < vmax) {
            unsigned long long nlx = pk2(-lx, -lx);
            unsigned long long nly = pk2(-ly, -ly);
            unsigned long long nlz = pk2(-lz, -lz);
            unsigned long long nk = 0;
#pragma unroll
            for (int q = 0; q < 8; q++) {
                unsigned long long dx = addx2(PX[q], nlx);
                unsigned long long dy = addx2(PY[q], nly);
                unsigned long long dz = addx2(PZ[q], nlz);
                unsigned long long s = addx2(addx2(mulx2(dx,dx), mulx2(dy,dy)), mulx2(dz,dz));
                float d0, d1; upk2(s, d0, d1);
                float v0 = fminf(md[2*q], d0);   md[2*q]   = v0;
                float v1 = fminf(md[2*q+1], d1); md[2*q+1] = v1;
                nk = umax64(nk, ((unsigned long long)__float_as_uint(v0) << 32) | NO[2*q]);
                nk = umax64(nk, ((unsigned long long)__float_as_uint(v1) << 32) | NO[2*q+1]);
            }
            key = nk;
        }
        unsigned hi = (unsigned)(key >> 32), lo = (unsigned)key;
        unsigned mhi = __reduce_max_sync(0xffffffffu, hi);
        unsigned mlo = __reduce_max_sync(0xffffffffu, (hi == mhi) ? lo : 0u);
        if (lane == 0) swk[par * 8 + w] = ((unsigned long long)mhi << 32) | mlo;
        __syncthreads();
        const ulonglong2* kp = (const ulonglong2*)(swk + par * 8);
        ulonglong2 v0 = kp[0], v1 = kp[1], v2 = kp[2], v3 = kp[3];
        unsigned long long best = umax64(umax64(umax64(v0.x, v0.y), umax64(v1.x, v1.y)),
                                         umax64(umax64(v2.x, v2.y), umax64(v3.x, v3.y)));
        unsigned wi = ~(unsigned)best;
        if (t == 0) g_idx[b * Mm + m] = (int)wi;
        float4 c4 = op4[wi];
        lx = c4.x; ly = c4.y; lz = c4.z;
        par ^= 1;
    }
}

// ---------------- K2: grid-pruned radius search + exact 32-smallest ----------------
__global__ void __launch_bounds__(256) k2_nbr(const float* __restrict__ pos,
                                              const float* __restrict__ norm,
                                              float* __restrict__ out_pos,
                                              float* __restrict__ out_norm) {
    __shared__ unsigned long long keys[8][CAP];
    __shared__ int wcnt[8];

    int b = blockIdx.y, t = threadIdx.x;
    int w = t >> 5, lane = t & 31;
    int m = blockIdx.x * 8 + w;
    int ci = g_idx[b * Mm + m];
    const float* pc = pos + ((size_t)b * Nn + ci) * 3;
    float cx = pc[0], cy = pc[1], cz = pc[2];
    if (lane == 0) {
        wcnt[w] = 0;
        size_t o = ((size_t)b * Mm + m) * 3;
        out_pos[o] = cx; out_pos[o+1] = cy; out_pos[o+2] = cz;
        const float* nc_ = norm + ((size_t)b * Nn + ci) * 3;
        out_norm[o] = nc_[0]; out_norm[o+1] = nc_[1]; out_norm[o+2] = nc_[2];
    }
    __syncwarp();
    float cs = __fadd_rn(__fadd_rn(__fmul_rn(cx,cx), __fmul_rn(cy,cy)), __fmul_rn(cz,cz));

    int ix0 = max(0, (int)floorf((cx - 0.21f) * 16.f)), ix1 = min(15, (int)floorf((cx + 0.21f) * 16.f));
    int iy0 = max(0, (int)floorf((cy - 0.21f) * 16.f)), iy1 = min(15, (int)floorf((cy + 0.21f) * 16.f));
    int iz0 = max(0, (int)floorf((cz - 0.21f) * 16.f)), iz1 = min(15, (int)floorf((cz + 0.21f) * 16.f));
    int nx = ix1 - ix0 + 1, ny = iy1 - iy0 + 1, nz = iz1 - iz0 + 1;
    const int cb_ = b * (NC + 1);
    const int pb_ = b * Nn;

    for (int cc = lane; cc < 512; cc += 32) {
        int dx_ = cc & 7, dy_ = (cc >> 3) & 7, dz_ = cc >> 6;
        if (dx_ < nx && dy_ < ny && dz_ < nz) {
            int cell = mspread4(ix0 + dx_) | (mspread4(iy0 + dy_) << 1) | (mspread4(iz0 + dz_) << 2);
            int s = g_cst[cb_ + cell], e = g_cst[cb_ + cell + 1];
            for (int i = s; i < e; i++) {
                float px = g_sx[pb_ + i], py = g_sy[pb_ + i], pz = g_sz[pb_ + i];
                float ps = __fadd_rn(__fadd_rn(__fmul_rn(px,px), __fmul_rn(py,py)), __fmul_rn(pz,pz));
                float dot = __fadd_rn(__fadd_rn(__fmul_rn(cx,px), __fmul_rn(cy,py)), __fmul_rn(cz,pz));
                float d2 = __fsub_rn(__fadd_rn(cs, ps), __fmul_rn(2.0f, dot));
                if (d2 <= 0.04f) {
                    int slot = atomicAdd(&wcnt[w], 1);
                    unsigned u = __float_as_uint(d2);
                    u ^= ((unsigned)(((int)u) >> 31)) | 0x80000000u;
                    if (slot < CAP)
                        keys[w][slot] = ((unsigned long long)u << 32) | (unsigned)g_sor[pb_ + i];
                }
            }
        }
    }
    __syncwarp();
    int cnt = min(wcnt[w], CAP);
    int outn = cnt < KN ? cnt : KN;
    size_t nb = ((size_t)b * Mm + m) * KN;
    for (int r = 0; r < outn; r++) {
        unsigned long long best = 0xFFFFFFFFFFFFFFFFull;
        for (int i = lane; i < cnt; i += 32) best = umin64(best, keys[w][i]);
#pragma unroll
        for (int o = 16; o > 0; o >>= 1) best = umin64(best, __shfl_xor_sync(0xffffffffu, best, o));
        if (lane == 0) g_nbr[nb + r] = (int)(unsigned)best;
        for (int i = lane; i < cnt; i += 32)
            if (keys[w][i] == best) keys[w][i] = 0xFFFFFFFFFFFFFFFFull;
        __syncwarp();
    }
    for (int r2 = outn + lane; r2 < KN; r2 += 32) g_nbr[nb + r2] = -1;
}

// ---------------- K3: fused PPF + MLP + max (transposed h1, 4 FFMA2 chains) ----------------
__device__ __forceinline__ float get_angle(float ax, float ay, float az,
                                           float bx, float by, float bz) {
    float cx = ay*bz - az*by;
    float cy = az*bx - ax*bz;
    float cz = ax*by - ay*bx;
    float cn2 = cx*cx + cy*cy + cz*cz;
    float cn = cn2 > 0.f ? sqrtf(cn2) : 0.f;
    float d = ax*bx + ay*by + az*bz;
    if (cn == 0.f && d == 0.f) d = 1.f;
    return atan2f(cn, d);
}

__global__ void __launch_bounds__(256) k3_mlp(const float* __restrict__ pos,
                                              const float* __restrict__ norm,
                                              const float* __restrict__ W1,
                                              const float* __restrict__ W2,
                                              const float* __restrict__ b2,
                                              const float* __restrict__ out_pos,
                                              const float* __restrict__ out_norm,
                                              float* __restrict__ out) {
    extern __shared__ char sm3[];
    float4* shT = (float4*)sm3;                   // [16][256] float4: h1T[q][pp]
    int* snbr = (int*)(sm3 + 16 * 256 * 16);      // 256
    int* scnt = snbr + 256;                       // 8
    float* sW1p = (float*)(scnt + 8);             // 4x64 (W1 rows 64..67)
    float* scp = sW1p + 256;                      // 8x3
    float* scn = scp + 24;                        // 8x3

    int t = threadIdx.x, b = blockIdx.y;
    int cb = blockIdx.x * 8;
    snbr[t] = g_nbr[((size_t)b * Mm + cb) * KN + t];
    sW1p[t] = W1[64 * 64 + t];
    if (t < 24) {
        size_t o = ((size_t)b * Mm + cb) * 3 + t;
        scp[t] = out_pos[o];
        scn[t] = out_norm[o];
    }
    __syncthreads();

    { // phase A: thread = (center g, neighbor k) -> h1 row into transposed smem
        int g = t >> 5, lane = t & 31;
        int j = snbr[t];
        unsigned msk = __ballot_sync(0xffffffffu, j >= 0);
        if (lane == 0) scnt[g] = __popc(msk);   // front-packed
        if (j >= 0) {
            float cx = scp[g*3], cy = scp[g*3+1], cz = scp[g*3+2];
            float nix = scn[g*3], niy = scn[g*3+1], niz = scn[g*3+2];
            size_t pj = ((size_t)b * Nn + j) * 3;
            float dx = pos[pj] - cx, dy = pos[pj+1] - cy, dz = pos[pj+2] - cz;
            float njx = norm[pj], njy = norm[pj+1], njz = norm[pj+2];
            float dd = dx*dx + dy*dy + dz*dz;
            float f0 = dd > 0.f ? sqrtf(dd) : 0.f;
            float f1 = get_angle(nix, niy, niz, dx, dy, dz);
            float f2 = get_angle(njx, njy, njz, dx, dy, dz);
            float f3 = get_angle(nix, niy, niz, njx, njy, njz);
            const float4* Ar = (const float4*)(g_A + ((size_t)b * Nn + j) * 64);
            const float4* w1p = (const float4*)sW1p;
#pragma unroll
            for (int q = 0; q < 16; q++) {
                float4 a = Ar[q];
                float4 w0 = w1p[q], w1v = w1p[16+q], w2v = w1p[32+q], w3v = w1p[48+q];
                a.x = fmaxf(fmaf(f3,w3v.x, fmaf(f2,w2v.x, fmaf(f1,w1v.x, fmaf(f0,w0.x, a.x)))), 0.f);
                a.y = fmaxf(fmaf(f3,w3v.y, fmaf(f2,w2v.y, fmaf(f1,w1v.y, fmaf(f0,w0.y, a.y)))), 0.f);
                a.z = fmaxf(fmaf(f3,w3v.z, fmaf(f2,w2v.z, fmaf(f1,w1v.z, fmaf(f0,w0.z, a.z)))), 0.f);
                a.w = fmaxf(fmaf(f3,w3v.w, fmaf(f2,w2v.w, fmaf(f1,w1v.w, fmaf(f0,w0.w, a.w)))), 0.f);
                shT[q * 256 + t] = a;   // consecutive t -> conflict-free STS.128
            }
        }
    }
    __syncthreads();

    { // phase C: thread = (g-half, out channel); 4 independent FFMA2 chains (q split)
        int c = t & 127, gh = t >> 7;
        unsigned long long w2p[32];
#pragma unroll
        for (int i = 0; i < 32; i++)
            w2p[i] = pk2(W2[(2*i) * 128 + c], W2[(2*i+1) * 128 + c]);
        float bb2 = b2[c];
#pragma unroll
        for (int g0 = 0; g0 < 8; g0 += 2) {
            int gg = g0 + gh;
            int kn = scnt[gg];                    // warp-uniform
            float mx = __int_as_float(0xff800000);
            const float4* hrow = shT + gg * 32;
            for (int k = 0; k < kn; k++) {
                unsigned long long a01 = pk2(bb2, 0.f), a23 = pk2(0.f, 0.f);
                unsigned long long c01 = pk2(0.f, 0.f), c23 = pk2(0.f, 0.f);
#pragma unroll
                for (int q = 0; q < 8; q++) {
                    float4 ha = hrow[q * 256 + k];
                    float4 hb = hrow[(q + 8) * 256 + k];
                    a01 = fmax2(pk2(ha.x, ha.y), w2p[2*q],      a01);
                    a23 = fmax2(pk2(ha.z, ha.w), w2p[2*q+1],    a23);
                    c01 = fmax2(pk2(hb.x, hb.y), w2p[2*(q+8)],  c01);
                    c23 = fmax2(pk2(hb.z, hb.w), w2p[2*(q+8)+1], c23);
                }
                unsigned long long s01 = addx2(a01, c01);
                unsigned long long s23 = addx2(a23, c23);
                float z0, z1, z2, z3;
                upk2(s01, z0, z1); upk2(s23, z2, z3);
                mx = fmaxf(mx, (z0 + z1) + (z2 + z3));
            }
            out[((size_t)(b * Mm + cb + gg)) * 128 + c] = fmaxf(mx, 0.f);
        }
    }
}

extern "C" void kernel_launch(void* const* d_in, const int* in_sizes, int n_in,
                              void* d_out, int out_size) {
    const float* x    = (const float*)d_in[0];
    const float* pos  = (const float*)d_in[1];
    const float* norm = (const float*)d_in[2];
    const float* W1   = (const float*)d_in[3];
    const float* b1   = (const float*)d_in[4];
    const float* W2   = (const float*)d_in[5];
    const float* b2   = (const float*)d_in[6];

    float* out      = (float*)d_out;
    float* out_pos  = out + (size_t)Bz * Mm * H2;
    float* out_norm = out_pos + (size_t)Bz * Mm * 3;

    const int smem1 = 128 + Nn * 16 + 3 * Nn * 4 + Nn * 4 + (NC + 1 + NC + 256) * 4;
    const int smem3 = 16 * 256 * 16 + 256 * 4 + 8 * 4 + 256 * 4 + 48 * 4;

    cudaFuncSetAttribute(k1_fps, cudaFuncAttributeMaxDynamicSharedMemorySize, smem1);
    cudaFuncSetAttribute(k3_mlp, cudaFuncAttributeMaxDynamicSharedMemorySize, smem3);

    k0_feat<<<(Bz * Nn) / 128, 256>>>(x, W1, b1);
    k1_fps<<<Bz, 256, smem1>>>(pos);
    k2_nbr<<<dim3(Mm / 8, Bz), 256>>>(pos, norm, out_pos, out_norm);
    k3_mlp<<<dim3(Mm / 8, Bz), 256, smem3>>>(pos, norm, W1, W2, b2, out_pos, out_norm, out);
}

// round 12
// speedup vs baseline: 1.0428x; 1.0428x over previous
#include <cuda_runtime.h>
#include <math.h>
#include <stdint.h>

#define Bz 8
#define Nn 4096
#define Mm 2048
#define H2 128
#define KN 32
#define CAP 512
#define NC 4096   // 16^3 morton cells

__device__ float g_A[Bz * Nn * 64];     // x @ W1[:64] + b1
__device__ int   g_idx[Bz * Mm];        // FPS indices
__device__ int   g_nbr[Bz * Mm * KN];   // in-radius neighbors, front-packed, -1 pad
// morton-sorted point data exported by k1 for k2's grid search
__device__ float g_sx[Bz * Nn];
__device__ float g_sy[Bz * Nn];
__device__ float g_sz[Bz * Nn];
__device__ int   g_sor[Bz * Nn];
__device__ int   g_cst[Bz * (NC + 1)];

__device__ __forceinline__ unsigned long long umax64(unsigned long long a, unsigned long long b){return a>b?a:b;}
__device__ __forceinline__ unsigned long long umin64(unsigned long long a, unsigned long long b){return a<b?a:b;}

// packed f32x2 helpers (rn rounding identical to scalar)
__device__ __forceinline__ unsigned long long pk2(float lo, float hi){
    unsigned long long r; asm("mov.b64 %0, {%1, %2};" : "=l"(r) : "f"(lo), "f"(hi)); return r;
}
__device__ __forceinline__ void upk2(unsigned long long v, float& lo, float& hi){
    asm("mov.b64 {%0, %1}, %2;" : "=f"(lo), "=f"(hi) : "l"(v));
}
__device__ __forceinline__ unsigned long long addx2(unsigned long long a, unsigned long long b){
    unsigned long long r; asm("add.rn.f32x2 %0, %1, %2;" : "=l"(r) : "l"(a), "l"(b)); return r;
}
__device__ __forceinline__ unsigned long long mulx2(unsigned long long a, unsigned long long b){
    unsigned long long r; asm("mul.rn.f32x2 %0, %1, %2;" : "=l"(r) : "l"(a), "l"(b)); return r;
}
__device__ __forceinline__ unsigned long long fmax2(unsigned long long a, unsigned long long b, unsigned long long c){
    unsigned long long r; asm("fma.rn.f32x2 %0, %1, %2, %3;" : "=l"(r) : "l"(a), "l"(b), "l"(c)); return r;
}

__device__ __forceinline__ int mspread4(int v){  // 4-bit spread for 16^3 morton
    return (v & 1) | ((v & 2) << 2) | ((v & 4) << 4) | ((v & 8) << 6);
}

// ---------------- K0: A = x @ W1[0:64,:] + b1 ----------------
__global__ void __launch_bounds__(256) k0_feat(const float* __restrict__ x,
                                               const float* __restrict__ W1,
                                               const float* __restrict__ b1) {
    __shared__ float xs[4 * 64];
    int t = threadIdx.x;
    int c = t & 63, rs = t >> 6;
    float w[64];
#pragma unroll
    for (int f = 0; f < 64; f++) w[f] = W1[f * 64 + c];
    float bb = b1[c];
    int base = blockIdx.x * 128;
    const float4* xs4 = (const float4*)xs;
    for (int r0 = 0; r0 < 128; r0 += 4) {
        int row = base + r0 + rs;
        __syncthreads();
        xs[rs * 64 + c] = x[(size_t)row * 64 + c];
        __syncthreads();
        float a0 = bb, a1 = 0.f, a2 = 0.f, a3 = 0.f;
#pragma unroll
        for (int q = 0; q < 16; q++) {
            float4 xv = xs4[rs * 16 + q];
            a0 = fmaf(xv.x, w[4*q+0], a0);
            a1 = fmaf(xv.y, w[4*q+1], a1);
            a2 = fmaf(xv.z, w[4*q+2], a2);
            a3 = fmaf(xv.w, w[4*q+3], a3);
        }
        g_A[(size_t)row * 64 + c] = (a0 + a1) + (a2 + a3);
    }
}

// ---------------- K1: FPS (R8 engine) + export sorted grid for k2 ----------------
// md update arithmetic bit-identical to the passing brute-force version.
__global__ void __launch_bounds__(256) k1_fps(const float* __restrict__ pos) {
    extern __shared__ char sm1c[];
    unsigned long long* swk = (unsigned long long*)sm1c;       // [2][8]
    float4* op4 = (float4*)(sm1c + 128);                       // [Nn] original order
    float* sx = (float*)(sm1c + 128 + Nn * 16);                // morton-sorted
    float* sy = sx + Nn;
    float* sz = sy + Nn;
    int* sorig  = (int*)(sz + Nn);
    int* cstart = sorig + Nn;      // NC+1
    int* ccnt   = cstart + NC + 1; // NC
    int* stmp   = ccnt + NC;       // 256

    int b = blockIdx.x, t = threadIdx.x;
    int w = t >> 5, lane = t & 31;
    const float* p = pos + (size_t)b * Nn * 3;

    for (int i = t; i < Nn; i += 256)
        op4[i] = make_float4(p[i*3], p[i*3+1], p[i*3+2], 0.f);
    for (int i = t; i < NC; i += 256) ccnt[i] = 0;
    __syncthreads();
    for (int i = t; i < Nn; i += 256) {
        float4 q = op4[i];
        int ix = min(15, max(0, (int)(q.x * 16.0f)));
        int iy = min(15, max(0, (int)(q.y * 16.0f)));
        int iz = min(15, max(0, (int)(q.z * 16.0f)));
        atomicAdd(&ccnt[mspread4(ix) | (mspread4(iy) << 1) | (mspread4(iz) << 2)], 1);
    }
    __syncthreads();
    int psum = 0;
#pragma unroll
    for (int k = 0; k < 16; k++) psum += ccnt[t * 16 + k];
    stmp[t] = psum;
    __syncthreads();
    for (int off = 1; off < 256; off <<= 1) {
        int v = stmp[t];
        if (t >= off) v += stmp[t - off];
        __syncthreads();
        stmp[t] = v;
        __syncthreads();
    }
    int run = stmp[t] - psum;
#pragma unroll
    for (int k = 0; k < 16; k++) {
        int c = ccnt[t * 16 + k];
        cstart[t * 16 + k] = run;
        g_cst[b * (NC + 1) + t * 16 + k] = run;
        run += c;
    }
    if (t == 255) { cstart[NC] = Nn; g_cst[b * (NC + 1) + NC] = Nn; }
    __syncthreads();
    for (int i = t; i < NC; i += 256) ccnt[i] = 0;
    __syncthreads();
    for (int i = t; i < Nn; i += 256) {
        float4 q = op4[i];
        int ix = min(15, max(0, (int)(q.x * 16.0f)));
        int iy = min(15, max(0, (int)(q.y * 16.0f)));
        int iz = min(15, max(0, (int)(q.z * 16.0f)));
        int c = mspread4(ix) | (mspread4(iy) << 1) | (mspread4(iz) << 2);
        int dst = cstart[c] + atomicAdd(&ccnt[c], 1);
        sx[dst] = q.x; sy[dst] = q.y; sz[dst] = q.z;
        sorig[dst] = i;
        g_sx[b * Nn + dst] = q.x; g_sy[b * Nn + dst] = q.y; g_sz[b * Nn + dst] = q.z;
        g_sor[b * Nn + dst] = i;
    }
    if (t == 0) g_idx[b * Mm] = 0;
    __syncthreads();

    // pack 16 sorted points per thread as 8 f32x2 pairs; tight bbox in regs
    unsigned long long PX[8], PY[8], PZ[8];
    float md[16];
    unsigned NO[16];
    int base = t * 16;
    float bx0 = 1e30f, bx1 = -1e30f, by0 = 1e30f, by1 = -1e30f, bz0 = 1e30f, bz1 = -1e30f;
#pragma unroll
    for (int q = 0; q < 8; q++) {
        float a0 = sx[base + 2*q], a1 = sx[base + 2*q + 1];
        float c0 = sy[base + 2*q], c1 = sy[base + 2*q + 1];
        float d0 = sz[base + 2*q], d1 = sz[base + 2*q + 1];
        PX[q] = pk2(a0, a1); PY[q] = pk2(c0, c1); PZ[q] = pk2(d0, d1);
        bx0 = fminf(bx0, fminf(a0, a1)); bx1 = fmaxf(bx1, fmaxf(a0, a1));
        by0 = fminf(by0, fminf(c0, c1)); by1 = fmaxf(by1, fmaxf(c0, c1));
        bz0 = fminf(bz0, fminf(d0, d1)); bz1 = fmaxf(bz1, fmaxf(d0, d1));
        NO[2*q]   = ~(unsigned)sorig[base + 2*q];
        NO[2*q+1] = ~(unsigned)sorig[base + 2*q + 1];
        md[2*q] = __int_as_float(0x7f800000);
        md[2*q+1] = __int_as_float(0x7f800000);
    }
    unsigned long long key = 0;
#pragma unroll
    for (int i = 0; i < 16; i++)
        key = umax64(key, (0x7f800000ULL << 32) | NO[i]);

    float4 ctr = op4[0];
    float lx = ctr.x, ly = ctr.y, lz = ctr.z;
    unsigned par = 0;

    for (int m = 1; m < Mm; m++) {
        float vmax = __uint_as_float((unsigned)(key >> 32));
        float lbx = fmaxf(fmaxf(bx0 - lx, lx - bx1), 0.f);
        float lby = fmaxf(fmaxf(by0 - ly, ly - by1), 0.f);
        float lbz = fmaxf(fmaxf(bz0 - lz, lz - bz1), 0.f);
        float lb2 = (lbx*lbx + lby*lby + lbz*lbz) * 0.999f;
        if (lb2 < vmax) {
            unsigned long long nlx = pk2(-lx, -lx);
            unsigned long long nly = pk2(-ly, -ly);
            unsigned long long nlz = pk2(-lz, -lz);
            unsigned long long nk = 0;
#pragma unroll
            for (int q = 0; q < 8; q++) {
                unsigned long long dx = addx2(PX[q], nlx);
                unsigned long long dy = addx2(PY[q], nly);
                unsigned long long dz = addx2(PZ[q], nlz);
                unsigned long long s = addx2(addx2(mulx2(dx,dx), mulx2(dy,dy)), mulx2(dz,dz));
                float d0, d1; upk2(s, d0, d1);
                float v0 = fminf(md[2*q], d0);   md[2*q]   = v0;
                float v1 = fminf(md[2*q+1], d1); md[2*q+1] = v1;
                nk = umax64(nk, ((unsigned long long)__float_as_uint(v0) << 32) | NO[2*q]);
                nk = umax64(nk, ((unsigned long long)__float_as_uint(v1) << 32) | NO[2*q+1]);
            }
            key = nk;
        }
        unsigned hi = (unsigned)(key >> 32), lo = (unsigned)key;
        unsigned mhi = __reduce_max_sync(0xffffffffu, hi);
        unsigned mlo = __reduce_max_sync(0xffffffffu, (hi == mhi) ? lo : 0u);
        if (lane == 0) swk[par * 8 + w] = ((unsigned long long)mhi << 32) | mlo;
        __syncthreads();
        const ulonglong2* kp = (const ulonglong2*)(swk + par * 8);
        ulonglong2 v0 = kp[0], v1 = kp[1], v2 = kp[2], v3 = kp[3];
        unsigned long long best = umax64(umax64(umax64(v0.x, v0.y), umax64(v1.x, v1.y)),
                                         umax64(umax64(v2.x, v2.y), umax64(v3.x, v3.y)));
        unsigned wi = ~(unsigned)best;
        if (t == 0) g_idx[b * Mm + m] = (int)wi;
        float4 c4 = op4[wi];
        lx = c4.x; ly = c4.y; lz = c4.z;
        par ^= 1;
    }
}

// ---------------- K2: grid-pruned radius search + exact 32-smallest ----------------
__global__ void __launch_bounds__(256) k2_nbr(const float* __restrict__ pos,
                                              const float* __restrict__ norm,
                                              float* __restrict__ out_pos,
                                              float* __restrict__ out_norm) {
    __shared__ unsigned long long keys[8][CAP];
    __shared__ int wcnt[8];

    int b = blockIdx.y, t = threadIdx.x;
    int w = t >> 5, lane = t & 31;
    int m = blockIdx.x * 8 + w;
    int ci = g_idx[b * Mm + m];
    const float* pc = pos + ((size_t)b * Nn + ci) * 3;
    float cx = pc[0], cy = pc[1], cz = pc[2];
    if (lane == 0) {
        wcnt[w] = 0;
        size_t o = ((size_t)b * Mm + m) * 3;
        out_pos[o] = cx; out_pos[o+1] = cy; out_pos[o+2] = cz;
        const float* nc_ = norm + ((size_t)b * Nn + ci) * 3;
        out_norm[o] = nc_[0]; out_norm[o+1] = nc_[1]; out_norm[o+2] = nc_[2];
    }
    __syncwarp();
    float cs = __fadd_rn(__fadd_rn(__fmul_rn(cx,cx), __fmul_rn(cy,cy)), __fmul_rn(cz,cz));

    int ix0 = max(0, (int)floorf((cx - 0.21f) * 16.f)), ix1 = min(15, (int)floorf((cx + 0.21f) * 16.f));
    int iy0 = max(0, (int)floorf((cy - 0.21f) * 16.f)), iy1 = min(15, (int)floorf((cy + 0.21f) * 16.f));
    int iz0 = max(0, (int)floorf((cz - 0.21f) * 16.f)), iz1 = min(15, (int)floorf((cz + 0.21f) * 16.f));
    int nx = ix1 - ix0 + 1, ny = iy1 - iy0 + 1, nz = iz1 - iz0 + 1;
    const int cb_ = b * (NC + 1);
    const int pb_ = b * Nn;

    for (int cc = lane; cc < 512; cc += 32) {
        int dx_ = cc & 7, dy_ = (cc >> 3) & 7, dz_ = cc >> 6;
        if (dx_ < nx && dy_ < ny && dz_ < nz) {
            int cell = mspread4(ix0 + dx_) | (mspread4(iy0 + dy_) << 1) | (mspread4(iz0 + dz_) << 2);
            int s = g_cst[cb_ + cell], e = g_cst[cb_ + cell + 1];
            for (int i = s; i < e; i++) {
                float px = g_sx[pb_ + i], py = g_sy[pb_ + i], pz = g_sz[pb_ + i];
                float ps = __fadd_rn(__fadd_rn(__fmul_rn(px,px), __fmul_rn(py,py)), __fmul_rn(pz,pz));
                float dot = __fadd_rn(__fadd_rn(__fmul_rn(cx,px), __fmul_rn(cy,py)), __fmul_rn(cz,pz));
                float d2 = __fsub_rn(__fadd_rn(cs, ps), __fmul_rn(2.0f, dot));
                if (d2 <= 0.04f) {
                    int slot = atomicAdd(&wcnt[w], 1);
                    unsigned u = __float_as_uint(d2);
                    u ^= ((unsigned)(((int)u) >> 31)) | 0x80000000u;
                    if (slot < CAP)
                        keys[w][slot] = ((unsigned long long)u << 32) | (unsigned)g_sor[pb_ + i];
                }
            }
        }
    }
    __syncwarp();
    int cnt = min(wcnt[w], CAP);
    int outn = cnt < KN ? cnt : KN;
    size_t nb = ((size_t)b * Mm + m) * KN;
    for (int r = 0; r < outn; r++) {
        unsigned long long best = 0xFFFFFFFFFFFFFFFFull;
        for (int i = lane; i < cnt; i += 32) best = umin64(best, keys[w][i]);
#pragma unroll
        for (int o = 16; o > 0; o >>= 1) best = umin64(best, __shfl_xor_sync(0xffffffffu, best, o));
        if (lane == 0) g_nbr[nb + r] = (int)(unsigned)best;
        for (int i = lane; i < cnt; i += 32)
            if (keys[w][i] == best) keys[w][i] = 0xFFFFFFFFFFFFFFFFull;
        __syncwarp();
    }
    for (int r2 = outn + lane; r2 < KN; r2 += 32) g_nbr[nb + r2] = -1;
}

// ---------------- K3: fused PPF + MLP + max (transposed h1, channel-pair f32x2;
//                   2 warps per gg -> half the broadcast LDS traffic) ----------------
__device__ __forceinline__ float get_angle(float ax, float ay, float az,
                                           float bx, float by, float bz) {
    float cx = ay*bz - az*by;
    float cy = az*bx - ax*bz;
    float cz = ax*by - ay*bx;
    float cn2 = cx*cx + cy*cy + cz*cz;
    float cn = cn2 > 0.f ? sqrtf(cn2) : 0.f;
    float d = ax*bx + ay*by + az*bz;
    if (cn == 0.f && d == 0.f) d = 1.f;
    return atan2f(cn, d);
}

__global__ void __launch_bounds__(256, 1) k3_mlp(const float* __restrict__ pos,
                                                 const float* __restrict__ norm,
                                                 const float* __restrict__ W1,
                                                 const float* __restrict__ W2,
                                                 const float* __restrict__ b2,
                                                 const float* __restrict__ out_pos,
                                                 const float* __restrict__ out_norm,
                                                 float* __restrict__ out) {
    extern __shared__ char sm3[];
    float4* shT = (float4*)sm3;                   // [16][256] float4: h1T[q][pp]
    int* snbr = (int*)(sm3 + 16 * 256 * 16);      // 256
    int* scnt = snbr + 256;                       // 8
    float* sW1p = (float*)(scnt + 8);             // 4x64 (W1 rows 64..67)
    float* scp = sW1p + 256;                      // 8x3
    float* scn = scp + 24;                        // 8x3

    int t = threadIdx.x, b = blockIdx.y;
    int cb = blockIdx.x * 8;
    snbr[t] = g_nbr[((size_t)b * Mm + cb) * KN + t];
    sW1p[t] = W1[64 * 64 + t];
    if (t < 24) {
        size_t o = ((size_t)b * Mm + cb) * 3 + t;
        scp[t] = out_pos[o];
        scn[t] = out_norm[o];
    }
    __syncthreads();

    { // phase A: thread = (center g, neighbor k) -> h1 row into transposed smem
        int g = t >> 5, lane = t & 31;
        int j = snbr[t];
        unsigned msk = __ballot_sync(0xffffffffu, j >= 0);
        if (lane == 0) scnt[g] = __popc(msk);   // front-packed
        if (j >= 0) {
            float cx = scp[g*3], cy = scp[g*3+1], cz = scp[g*3+2];
            float nix = scn[g*3], niy = scn[g*3+1], niz = scn[g*3+2];
            size_t pj = ((size_t)b * Nn + j) * 3;
            float dx = pos[pj] - cx, dy = pos[pj+1] - cy, dz = pos[pj+2] - cz;
            float njx = norm[pj], njy = norm[pj+1], njz = norm[pj+2];
            float dd = dx*dx + dy*dy + dz*dz;
            float f0 = dd > 0.f ? sqrtf(dd) : 0.f;
            float f1 = get_angle(nix, niy, niz, dx, dy, dz);
            float f2 = get_angle(njx, njy, njz, dx, dy, dz);
            float f3 = get_angle(nix, niy, niz, njx, njy, njz);
            const float4* Ar = (const float4*)(g_A + ((size_t)b * Nn + j) * 64);
            const float4* w1p = (const float4*)sW1p;
#pragma unroll
            for (int q = 0; q < 16; q++) {
                float4 a = Ar[q];
                float4 w0 = w1p[q], w1v = w1p[16+q], w2v = w1p[32+q], w3v = w1p[48+q];
                a.x = fmaxf(fmaf(f3,w3v.x, fmaf(f2,w2v.x, fmaf(f1,w1v.x, fmaf(f0,w0.x, a.x)))), 0.f);
                a.y = fmaxf(fmaf(f3,w3v.y, fmaf(f2,w2v.y, fmaf(f1,w1v.y, fmaf(f0,w0.y, a.y)))), 0.f);
                a.z = fmaxf(fmaf(f3,w3v.z, fmaf(f2,w2v.z, fmaf(f1,w1v.z, fmaf(f0,w0.z, a.z)))), 0.f);
                a.w = fmaxf(fmaf(f3,w3v.w, fmaf(f2,w2v.w, fmaf(f1,w1v.w, fmaf(f0,w0.w, a.w)))), 0.f);
                shT[q * 256 + t] = a;   // consecutive t -> conflict-free STS.128
            }
        }
    }
    __syncthreads();

    { // phase C: thread = (gh, channel-pair); each thread computes 2 adjacent channels
        int cp = t & 63, gh = t >> 6;      // 64 pairs = 128 channels; gh in 0..3
        int c0 = cp * 2;
        unsigned long long w2p[64];
#pragma unroll
        for (int q = 0; q < 64; q++) {
            float2 wv = *(const float2*)(W2 + q * 128 + c0);
            w2p[q] = pk2(wv.x, wv.y);
        }
        float2 bv = *(const float2*)(b2 + c0);
        unsigned long long binit = pk2(bv.x, bv.y);
        unsigned long long zinit = pk2(0.f, 0.f);
#pragma unroll
        for (int g0 = 0; g0 < 2; g0++) {
            int gg = gh * 2 + g0;
            int kn = scnt[gg];              // warp-uniform
            float mxa = __int_as_float(0xff800000);
            float mxb = __int_as_float(0xff800000);
            const float4* hrow = shT + gg * 32;
            for (int k = 0; k < kn; k++) {
                unsigned long long a0 = binit, a1 = zinit, a2 = zinit, a3 = zinit;
#pragma unroll
                for (int q4 = 0; q4 < 16; q4++) {
                    float4 h = hrow[q4 * 256 + k];
                    a0 = fmax2(pk2(h.x, h.x), w2p[4*q4+0], a0);
                    a1 = fmax2(pk2(h.y, h.y), w2p[4*q4+1], a1);
                    a2 = fmax2(pk2(h.z, h.z), w2p[4*q4+2], a2);
                    a3 = fmax2(pk2(h.w, h.w), w2p[4*q4+3], a3);
                }
                unsigned long long s = addx2(addx2(a0, a1), addx2(a2, a3));
                float za, zb; upk2(s, za, zb);
                mxa = fmaxf(mxa, za);
                mxb = fmaxf(mxb, zb);
            }
            float2 o;
            o.x = fmaxf(mxa, 0.f);
            o.y = fmaxf(mxb, 0.f);
            *(float2*)(out + ((size_t)(b * Mm + cb + gg)) * 128 + c0) = o;
        }
    }
}

extern "C" void kernel_launch(void* const* d_in, const int* in_sizes, int n_in,
                              void* d_out, int out_size) {
    const float* x    = (const float*)d_in[0];
    const float* pos  = (const float*)d_in[1];
    const float* norm = (const float*)d_in[2];
    const float* W1   = (const float*)d_in[3];
    const float* b1   = (const float*)d_in[4];
    const float* W2   = (const float*)d_in[5];
    const float* b2   = (const float*)d_in[6];

    float* out      = (float*)d_out;
    float* out_pos  = out + (size_t)Bz * Mm * H2;
    float* out_norm = out_pos + (size_t)Bz * Mm * 3;

    const int smem1 = 128 + Nn * 16 + 3 * Nn * 4 + Nn * 4 + (NC + 1 + NC + 256) * 4;
    const int smem3 = 16 * 256 * 16 + 256 * 4 + 8 * 4 + 256 * 4 + 48 * 4;

    cudaFuncSetAttribute(k1_fps, cudaFuncAttributeMaxDynamicSharedMemorySize, smem1);
    cudaFuncSetAttribute(k3_mlp, cudaFuncAttributeMaxDynamicSharedMemorySize, smem3);

    k0_feat<<<(Bz * Nn) / 128, 256>>>(x, W1, b1);
    k1_fps<<<Bz, 256, smem1>>>(pos);
    k2_nbr<<<dim3(Mm / 8, Bz), 256>>>(pos, norm, out_pos, out_norm);
    k3_mlp<<<dim3(Mm / 8, Bz), 256, smem3>>>(pos, norm, W1, W2, b2, out_pos, out_norm, out);
}